// round 17
// baseline (speedup 1.0000x reference)
#include <cuda_runtime.h>
#include <math.h>

#define BIMG 4
#define HP   74
#define IMGPIX 6400
#define BT   640

// sqrt(log2(e) / (2*2.5^2)): arg = -(d*S)^2 == d^2 * -log2(e)/12.5
#define SCALE_S 0.33972874f
// -ln2 / 49
#define NEG_LN2_49 (-1.4145860827753985e-02f)
// ln(49 * sqrt(2*pi*2.5^2)) : folds the dropped per-element scale back in
#define ENT_OFF 5.7270496f

// shared floats: xs[960] | dvs[640] | S2[7280 float2] | W2[3920 float2]
#define F_XS  0
#define F_DV  960
#define F_S   1600
#define F_W   16160
#define SMEM_BYTES (24000 * 4)

typedef unsigned long long ull;

__device__ __forceinline__ float ex2f(float x) {
    float y;
    asm("ex2.approx.f32 %0, %1;" : "=f"(y) : "f"(x));
    return y;
}
__device__ __forceinline__ float lg2f(float x) {
    float y;
    asm("lg2.approx.f32 %0, %1;" : "=f"(y) : "f"(x));
    return y;
}
__device__ __forceinline__ ull pack2(float lo, float hi) {
    ull r;
    asm("mov.b64 %0, {%1, %2};" : "=l"(r) : "f"(lo), "f"(hi));
    return r;
}
__device__ __forceinline__ void unpack2(ull p, float& lo, float& hi) {
    asm("mov.b64 {%0, %1}, %2;" : "=f"(lo), "=f"(hi) : "l"(p));
}
__device__ __forceinline__ ull add2(ull a, ull b) {
    ull r;
    asm("add.rn.f32x2 %0, %1, %2;" : "=l"(r) : "l"(a), "l"(b));
    return r;
}
__device__ __forceinline__ ull mul2(ull a, ull b) {
    ull r;
    asm("mul.rn.f32x2 %0, %1, %2;" : "=l"(r) : "l"(a), "l"(b));
    return r;
}

// ---------------------------------------------------------------------------
// One block per (band pair g, image b): output rows py0+3, py0+4 (py0 = 2g).
// 640 threads, 1 CTA/SM, 148 blocks. Bands interleaved as float2 throughout.
// Phase 3 uses packed f32x2 arithmetic (2 exps per wide op chain).
// ---------------------------------------------------------------------------
__global__ __launch_bounds__(BT, 1)
void entropy_pair_kernel(const float* __restrict__ x, float* __restrict__ out) {
    extern __shared__ float sm[];
    float*  xs  = sm + F_XS;
    float*  dvs = sm + F_DV;              // pre-scaled division values (8x80)
    float2* S2  = (float2*)(sm + F_S);    // [(r*80+xp)*13 + dc] -> (band0, band1)
    float2* W2  = (float2*)(sm + F_W);    // [(r*7+c)*80 + xp]   -> (band0, band1)

    const int tid = threadIdx.x;
    const int g   = blockIdx.x;        // 0..36
    const int b   = blockIdx.y;        // 0..3
    const int py0 = 2 * g;
    const float* img = x + b * IMGPIX;
    float* ob = out + b * IMGPIX;

    // -- 1: input loads first; zero S2; early border rows --------------------
    {
        float4* xs4 = (float4*)xs;
        const float4* img4 = (const float4*)img;
        for (int i = tid; i < 240; i += BT) {     // 12 rows * 20 float4
            int r = i / 20, c4 = i - r * 20;
            int row = py0 - 2 + r;
            xs4[i] = ((unsigned)row < 80u) ? img4[row * 20 + c4]
                                           : make_float4(0.f, 0.f, 0.f, 0.f);
        }
    }
    {
        float4* S4 = (float4*)S2;
        for (int i = tid; i < 14560 / 4; i += BT)
            S4[i] = make_float4(0.f, 0.f, 0.f, 0.f);
    }
    if (g == 0  && tid < 240) ob[tid] = 0.0f;             // rows 0..2
    if (g == 36 && tid < 240) ob[77 * 80 + tid] = 0.0f;   // rows 77..79
    __syncthreads();

    // -- 2: preprocessing (exact op order); store scaled ---------------------
    {
        int r = tid / 80, c = tid - (tid / 80) * 80;   // r = 0..7
        float sum = 0.0f;
        #pragma unroll
        for (int dy = 0; dy < 5; dy++) {
            const float* rowp = xs + (r + dy) * 80;
            #pragma unroll
            for (int dx = -2; dx <= 2; dx++) {
                int cc = c + dx;
                if ((unsigned)cc < 80u) sum = __fadd_rn(sum, rowp[cc]);
            }
        }
        float smooth = rintf(__fdiv_rn(sum, 25.0f));
        float cv     = xs[(r + 2) * 80 + c];
        float sharp  = rintf(fminf(fmaxf(
                          __fsub_rn(__fmul_rn(2.5f, cv), __fmul_rn(1.25f, smooth)),
                          0.0f), 255.0f));
        float divi   = rintf(fminf(fmaxf(
                          __fdiv_rn(__fmul_rn(sharp, 255.0f),
                                    __fadd_rn(smooth, 1e-8f)),
                          0.0f), 255.0f));
        dvs[tid] = __fmul_rn(divi, SCALE_S);
    }
    __syncthreads();

    // -- 3: KDE column sums for both bands, f32x2 packed ----------------------
    if (tid < 560) {
        int dc = tid / 80;             // 0..6
        int xp = tid - dc * 80;        // 0..79
        int xc = xp - 6 + dc;          // <= xp
        if (xc >= 0) {
            float vA[8];
            #pragma unroll
            for (int a = 0; a < 8; a++) vA[a] = dvs[a * 80 + xp];
            ull vA2[4], nA2[4], U2[4];
            #pragma unroll
            for (int j = 0; j < 4; j++) {
                vA2[j] = pack2(vA[2 * j], vA[2 * j + 1]);
                nA2[j] = pack2(-vA[2 * j], -vA[2 * j + 1]);
                U2[j]  = 0ull;
            }
            float V[8];
            float eA7[7], eA0[8], eB0[8], eB7[7];   // boundary exps
            #pragma unroll
            for (int bb = 0; bb < 8; bb++) {
                float vb  = dvs[bb * 80 + xc];
                float nvb = -vb;
                ull vb2  = pack2(vb, vb);
                ull nvb2 = pack2(nvb, nvb);
                ull Vb2  = 0ull;
                #pragma unroll
                for (int j = 0; j < 4; j++) {
                    ull d2   = add2(vA2[j], nvb2);   //  (vA - vb) pair
                    ull nd2  = add2(nA2[j], vb2);    // -(vA - vb) pair
                    ull arg2 = mul2(d2, nd2);        // -(d)^2 pair
                    float a0, a1;
                    unpack2(arg2, a0, a1);
                    float e0 = ex2f(a0);
                    float e1 = ex2f(a1);
                    ull e2 = pack2(e0, e1);
                    U2[j] = add2(U2[j], e2);
                    Vb2   = add2(Vb2, e2);
                    // boundary captures (compile-time; register extracts)
                    if (bb == 7) {                       // E[a][7], a<7
                        if (2 * j < 7)     eA7[2 * j]     = e0;
                        if (2 * j + 1 < 7) eA7[2 * j + 1] = e1;
                    }
                    if (bb == 0) {                       // E[a][0], a>0
                        if (2 * j > 0)     eA0[2 * j]     = e0;
                        eA0[2 * j + 1] = e1;
                    }
                    if (j == 0 && bb > 0) eB0[bb] = e0;  // E[0][bb]
                    if (j == 3 && bb < 7) eB7[bb] = e1;  // E[7][bb]
                }
                float vlo, vhi;
                unpack2(Vb2, vlo, vhi);
                V[bb] = vlo + vhi;
            }
            float U[8];
            #pragma unroll
            for (int j = 0; j < 4; j++) unpack2(U2[j], U[2 * j], U[2 * j + 1]);

            float2* Sd = S2 + xp * 13 + dc;
            #pragma unroll
            for (int r = 0; r < 7; r++)           // s0 = U[r]-E[r][7], s1 = U[r+1]-E[r+1][0]
                Sd[r * 1040] = make_float2(U[r] - eA7[r], U[r + 1] - eA0[r + 1]);
            if (dc < 6) {                         // mirror: column xc, offset 12-dc
                float2* Sm = S2 + xc * 13 + (12 - dc);
                #pragma unroll
                for (int r = 0; r < 7; r++)       // t0 = V[r]-E[7][r], t1 = V[r+1]-E[0][r+1]
                    Sm[r * 1040] = make_float2(V[r] - eB7[r], V[r + 1] - eB0[r + 1]);
            }
        }
    }
    __syncthreads();

    // -- 4: raw window sums via float2 prefix (one item per thread) ----------
    if (tid < 560) {                   // tid = r*80 + xp
        const float2* Sp = S2 + tid * 13;
        float2 pref[14];
        pref[0] = make_float2(0.f, 0.f);
        #pragma unroll
        for (int k = 0; k < 13; k++) {
            float2 s = Sp[k];
            pref[k + 1] = make_float2(pref[k].x + s.x, pref[k].y + s.y);
        }
        int r = tid / 80, xp = tid - (tid / 80) * 80;
        #pragma unroll
        for (int c = 0; c < 7; c++) {
            float2 w = make_float2(pref[13 - c].x - pref[6 - c].x,
                                   pref[13 - c].y - pref[6 - c].y);  // >= 1
            W2[(r * 7 + c) * 80 + xp] = w;
        }
    }
    __syncthreads();

    // -- 5: per-window 4 product chains in registers, 4 lg2, store -----------
    if (tid < 148) {
        int h  = tid / 74;             // band
        int xw = tid - h * 74;
        const float* Wf = (const float*)W2;
        float p0 = 1.f, p1 = 1.f, p2 = 1.f, p3 = 1.f;
        #pragma unroll
        for (int i = 0; i < 49; i++) {
            int r = i / 7, c = i - r * 7;
            float w = Wf[((r * 7 + c) * 80 + xw + c) * 2 + h];
            if      (i < 13) p0 *= w;          // products <= 49^13
            else if (i < 25) p1 *= w;
            else if (i < 37) p2 *= w;
            else             p3 *= w;
        }
        float t = lg2f(p0) + lg2f(p1) + lg2f(p2) + lg2f(p3);
        ob[(py0 + h + 3) * 80 + (xw + 3)] = fmaf(t, NEG_LN2_49, ENT_OFF);
    }
    // column borders of the two written rows: 0,1,2,77,78,79 (disjoint writes)
    if (tid >= 160 && tid < 172) {
        int k = tid - 160;
        int h = k / 6, j = k - h * 6;
        int col = (j < 3) ? j : (74 + j);
        ob[(py0 + h + 3) * 80 + col] = 0.0f;
    }
}

// ---------------------------------------------------------------------------
extern "C" void kernel_launch(void* const* d_in, const int* in_sizes, int n_in,
                              void* d_out, int out_size) {
    const float* x = (const float*)d_in[0];
    float* out     = (float*)d_out;

    cudaFuncSetAttribute(entropy_pair_kernel,
                         cudaFuncAttributeMaxDynamicSharedMemorySize, SMEM_BYTES);
    dim3 grid(37, BIMG);               // 148 blocks = 1 per SM
    entropy_pair_kernel<<<grid, BT, SMEM_BYTES>>>(x, out);
}